// round 6
// baseline (speedup 1.0000x reference)
#include <cuda_runtime.h>

// Problem constants
#define BB 16
#define GG 32
#define TT 180
#define NN 1024   // H*W
#define FF 1024
#define SCALE 0.04419417382415922f  // 512^-0.5
#define EPSF 1e-6f
#define CARRY 64  // blocks doing weight-reduction phase A

// ---------------- scratch (no allocs allowed) ----------------
__device__ __align__(16) float g_part[CARRY * 512];   // partial column sums of wq
__device__ __align__(16) float g_wa[512];             // wqs[c]*gamma[c]
__device__ __align__(16) float g_wg[32];              // per-group sum of wa
__device__ __align__(16) float g_Wsum[512];           // row sums of wo
__device__ float g_const1;                            // sum(wqs*beta) + sum(bq)
__device__ __align__(16) float g_P[BB * GG * NN];     // 2MB partial channel sums
__device__ float g_sum[BB * GG];
__device__ float g_sq[BB * GG];
__device__ float g_rs[BB * GG];
__device__ float g_d[BB];
__device__ __align__(16) float g_k[BB * FF];
__device__ __align__(16) float g_v[BB * FF];
__device__ int g_c1 = 0;      // phase-A ticket
__device__ int g_c2 = 0;      // k2+k3 ticket
__device__ int g_c3 = 0;      // k56 ticket
__device__ int g_flag1 = 0;   // g_wa/g_wg/g_const1/g_Wsum ready
__device__ int g_flag2 = 0;   // g_P/g_rs/g_d/g_k/g_v ready

// Single fused kernel. grid 1152, block 256.
//   bid [0,512):    k2 (x stats + weighted partials); bids [0,64) first run
//                   weight phase A; last of those finalizes -> flag1.
//   bid [512,640):  k/v GEMM (independent).
//   last of the 640: rs/d finalize -> flag2.
//   bid [640,1152): softmax-weighted average + output stream (waits flag2).
__global__ void __launch_bounds__(256, 6)
mega(const float* __restrict__ x, const float* __restrict__ cond,
     const float* __restrict__ gamma, const float* __restrict__ beta,
     const float* __restrict__ wq, const float* __restrict__ bq,
     const float* __restrict__ wk, const float* __restrict__ bk,
     const float* __restrict__ wv, const float* __restrict__ bv,
     const float* __restrict__ wo, const float* __restrict__ bo,
     float* __restrict__ out)
{
    __shared__ float smem[5824];   // 23.3KB: max of k3 (2*16*181), k56 (~2144), k2 (512)
    int t = threadIdx.x;
    int bid = blockIdx.x;
    int w = t >> 5, lane = t & 31;

    if (bid < 640) {
        if (bid < 512) {
            // ================= phase A carriers =================
            if (bid < CARRY) {
                int j = bid;
                float s0 = 0.f, s1 = 0.f;
#pragma unroll
                for (int r = 0; r < 8; r++) {
                    const float* row = wq + (size_t)(j * 8 + r) * 512;
                    s0 += row[t];
                    s1 += row[t + 256];
                }
                g_part[j * 512 + t] = s0;
                g_part[j * 512 + t + 256] = s1;

                // wo row sum: warp w owns row j*8+w
                const float* rp = wo + (size_t)(j * 8 + w) * 512;
                float r = 0.f;
#pragma unroll
                for (int i = 0; i < 16; i++) r += rp[lane + 32 * i];
#pragma unroll
                for (int off = 16; off; off >>= 1) r += __shfl_down_sync(0xffffffffu, r, off);
                if (lane == 0) g_Wsum[j * 8 + w] = r;

                __syncthreads();
                __threadfence();
                __shared__ int isLast1;
                if (t == 0) isLast1 = (atomicAdd(&g_c1, 1) == CARRY - 1);
                __syncthreads();
                if (isLast1) {
                    __threadfence();
                    float wqs0 = 0.f, wqs1 = 0.f;
#pragma unroll 8
                    for (int jj = 0; jj < CARRY; jj++) {
                        wqs0 += g_part[jj * 512 + t];
                        wqs1 += g_part[jj * 512 + t + 256];
                    }
                    float wa0 = wqs0 * gamma[t];
                    float wa1 = wqs1 * gamma[t + 256];
                    g_wa[t] = wa0;
                    g_wa[t + 256] = wa1;

                    smem[t] = wqs0 * beta[t] + bq[t] + wqs1 * beta[t + 256] + bq[t + 256];
                    __syncthreads();
                    for (int st = 128; st; st >>= 1) {
                        if (t < st) smem[t] += smem[t + st];
                        __syncthreads();
                    }
                    if (t == 0) { g_const1 = smem[0]; g_c1 = 0; }

                    float wg0 = wa0, wg1 = wa1;
#pragma unroll
                    for (int off = 8; off; off >>= 1) {
                        wg0 += __shfl_down_sync(0xffffffffu, wg0, off, 16);
                        wg1 += __shfl_down_sync(0xffffffffu, wg1, off, 16);
                    }
                    if ((t & 15) == 0) {
                        g_wg[t >> 4] = wg0;
                        g_wg[16 + (t >> 4)] = wg1;
                    }
                    __syncthreads();
                    __threadfence();
                    if (t == 0) *(volatile int*)&g_flag1 = 1;
                }
            }

            // ================= wait for weights =================
            if (t == 0) { while (*(volatile int*)&g_flag1 == 0) __nanosleep(64); }
            __syncthreads();
            __threadfence();

            // ================= k2 body =================
            int bg = bid;
            int g = bg & 31;
            const float4* xs = (const float4*)x + (size_t)bg * 16 * 256;

            float4 p = make_float4(0.f, 0.f, 0.f, 0.f);
            float sum = 0.f, sq = 0.f;
#pragma unroll
            for (int c = 0; c < 16; c++) {
                float wv_ = g_wa[g * 16 + c];
                float4 v = xs[c * 256 + t];
                sum += v.x + v.y + v.z + v.w;
                sq += v.x * v.x + v.y * v.y + v.z * v.z + v.w * v.w;
                p.x += wv_ * v.x; p.y += wv_ * v.y; p.z += wv_ * v.z; p.w += wv_ * v.w;
            }
            ((float4*)g_P)[bg * 256 + t] = p;

            __syncthreads();  // smem may still be in use by phase-A finalize path
            float* s1 = smem;
            float* s2 = smem + 256;
            s1[t] = sum; s2[t] = sq;
            __syncthreads();
            for (int st = 128; st; st >>= 1) {
                if (t < st) { s1[t] += s1[t + st]; s2[t] += s2[t + st]; }
                __syncthreads();
            }
            if (t == 0) { g_sum[bg] = s1[0]; g_sq[bg] = s2[0]; }
        } else {
            // ================= k3 body: k/v GEMM =================
            int bx = bid - 512;               // 0..127
            int mat = bx >> 6;                // 0 = k, 1 = v
            int ft = bx & 63;                 // f-tile of 16
            const float* W    = mat ? wv : wk;
            const float* bias = mat ? bv : bk;
            float* o          = mat ? g_v : g_k;

            float (*sw)[181] = (float (*)[181])smem;
            float (*sc)[181] = (float (*)[181])(smem + 16 * 181);
            int f0 = ft * 16;
            for (int i = t; i < 16 * 180; i += 256) {
                int r = i / 180, cc2 = i - r * 180;
                sw[r][cc2] = W[(size_t)(f0 + r) * TT + cc2];
                sc[r][cc2] = cond[r * TT + cc2];
            }
            __syncthreads();

            int fo = t & 15, bb = t >> 4;
            float acc = 0.f;
#pragma unroll 4
            for (int k = 0; k < TT; k++) acc += sw[fo][k] * sc[bb][k];
            o[bb * FF + f0 + fo] = acc + bias[f0 + fo];
        }

        // ============ common ticket: last of 640 finalizes rs/d, sets flag2 ============
        __syncthreads();
        __threadfence();
        __shared__ int isLast2;
        if (t == 0) isLast2 = (atomicAdd(&g_c2, 1) == 639);
        __syncthreads();
        if (!isLast2) return;
        __threadfence();

        const float inv = 1.f / 16384.f;
#pragma unroll
        for (int i = 0; i < 2; i++) {
            int idx = t + 256 * i;                 // (b*32+g)
            float mean = g_sum[idx] * inv;
            float var = g_sq[idx] * inv - mean * mean;
            float rs = rsqrtf(var + EPSF);
            g_rs[idx] = rs;
            smem[idx] = mean * rs * g_wg[idx & 31];
        }
        __syncthreads();
        float c1 = g_const1;
#pragma unroll
        for (int i = 0; i < 2; i++) {
            int b = w + 8 * i;
            float v = smem[b * 32 + lane];
#pragma unroll
            for (int off = 16; off; off >>= 1) v += __shfl_down_sync(0xffffffffu, v, off);
            if (lane == 0) g_d[b] = c1 - v;
        }
        if (t == 0) g_c2 = 0;
        __syncthreads();
        __threadfence();
        if (t == 0) *(volatile int*)&g_flag2 = 1;
        return;
    }

    // ================= k56: wait for flag2 =================
    int kb = bid - 640;          // 0..511
    int b  = kb >> 5;
    int ch = kb & 31;
    int n0 = ch * 32;

    if (t == 0) { while (*(volatile int*)&g_flag2 == 0) __nanosleep(128); }
    __syncthreads();
    __threadfence();

    float* sk  = smem;
    float* sv  = smem + 1024;
    float* sA  = smem + 2048;
    float* sS  = smem + 2080;
    float* srs = smem + 2112;

    ((float4*)sk)[t] = ((const float4*)(g_k + b * FF))[t];
    ((float4*)sv)[t] = ((const float4*)(g_v + b * FF))[t];
    if (t < 32) srs[t] = g_rs[b * 32 + t];
    float d = g_d[b];
    __syncthreads();

    // S for 4 n's per warp (lane = group)
#pragma unroll
    for (int i = 0; i < 4; i++) {
        int n = w * 4 + i;
        float ps = srs[lane] * g_P[((size_t)b * 32 + lane) * NN + n0 + n];
#pragma unroll
        for (int off = 16; off; off >>= 1) ps += __shfl_xor_sync(0xffffffffu, ps, off);
        if (lane == 0) sS[n] = (ps + d) * SCALE;
    }
    __syncthreads();

    // softmax-weighted average over f (no max-sub: logits tiny by construction)
#pragma unroll
    for (int i = 0; i < 4; i++) {
        int n = w * 4 + i;
        float s = sS[n];
        float l = 0.f, acc = 0.f;
#pragma unroll
        for (int j = 0; j < 8; j++) {
            float4 k4v = ((float4*)sk)[j * 32 + lane];
            float4 v4  = ((float4*)sv)[j * 32 + lane];
            float e0 = __expf(s * k4v.x), e1 = __expf(s * k4v.y);
            float e2 = __expf(s * k4v.z), e3 = __expf(s * k4v.w);
            l += e0 + e1 + e2 + e3;
            acc += v4.x * e0 + v4.y * e1 + v4.z * e2 + v4.w * e3;
        }
#pragma unroll
        for (int off = 16; off; off >>= 1) {
            l   += __shfl_xor_sync(0xffffffffu, l, off);
            acc += __shfl_xor_sync(0xffffffffu, acc, off);
        }
        if (lane == 0) sA[n] = acc / l;
    }
    __syncthreads();

    // elementwise stream: out[b, :, n0:n0+32] = x + Wsum[c]*A[n] + bo[c]
    int f4 = t & 7, c0 = t >> 3;
    const float4* xp = (const float4*)x + ((size_t)b * 512) * 256 + ch * 8;
    float4*       op = (float4*)out     + ((size_t)b * 512) * 256 + ch * 8;
    float4 a = ((float4*)sA)[f4];
#pragma unroll
    for (int it = 0; it < 16; it++) {
        int c = c0 + 32 * it;
        float wv_ = g_Wsum[c];
        float bb = bo[c];
        float4 xv = xp[(size_t)c * 256 + f4];
        float4 o;
        o.x = xv.x + wv_ * a.x + bb;
        o.y = xv.y + wv_ * a.y + bb;
        o.z = xv.z + wv_ * a.z + bb;
        o.w = xv.w + wv_ * a.w + bb;
        op[(size_t)c * 256 + f4] = o;
    }

    // ============ last k56 block resets flags for graph replay ============
    if (t == 0) {
        if (atomicAdd(&g_c3, 1) == 511) {
            g_c3 = 0;
            *(volatile int*)&g_flag1 = 0;
            *(volatile int*)&g_flag2 = 0;
        }
    }
}

extern "C" void kernel_launch(void* const* d_in, const int* in_sizes, int n_in,
                              void* d_out, int out_size) {
    const float* x     = (const float*)d_in[0];
    const float* cond  = (const float*)d_in[1];
    const float* gamma = (const float*)d_in[2];
    const float* beta  = (const float*)d_in[3];
    const float* wq    = (const float*)d_in[4];
    const float* bq    = (const float*)d_in[5];
    const float* wk    = (const float*)d_in[6];
    const float* bk    = (const float*)d_in[7];
    const float* wv    = (const float*)d_in[8];
    const float* bv    = (const float*)d_in[9];
    const float* wo    = (const float*)d_in[10];
    const float* bo    = (const float*)d_in[11];
    float* out = (float*)d_out;

    mega<<<1152, 256>>>(x, cond, gamma, beta, wq, bq, wk, bk, wv, bv, wo, bo, out);
}

// round 7
// speedup vs baseline: 1.3333x; 1.3333x over previous
#include <cuda_runtime.h>

// Problem constants
#define BB 16
#define GG 32
#define TT 180
#define NN 1024   // H*W
#define FF 1024
#define SCALE 0.04419417382415922f  // 512^-0.5
#define EPSF 1e-6f
#define CARRY 64  // blocks doing the wq/wo weight reduction

// ---------------- scratch (no allocs allowed) ----------------
__device__ __align__(16) float g_part[CARRY * 512];   // partial column sums of wq
__device__ __align__(16) float g_wa[512];             // wqs[c]*gamma[c]
__device__ __align__(16) float g_wg[32];              // per-group sum of wa
__device__ __align__(16) float g_Wsum[512];           // row sums of wo
__device__ float g_const1;                            // sum(wqs*beta) + sum(bq)
__device__ float g_sum[BB * GG];
__device__ float g_sq[BB * GG];
__device__ float g_rs[BB * GG];
__device__ float g_d[BB];
__device__ __align__(16) float g_k[BB * FF];
__device__ __align__(16) float g_v[BB * FF];
__device__ int g_c1 = 0;      // kA last-block ticket

// ---------------- kA: stats ∥ k/v GEMM ∥ weight reductions (all independent) ----------
// grid 704, block 256.
//   bid [0,512):    per-(b,g) x stats: sum, sumsq (needs NO weights).
//   bid [512,640):  k/v GEMM.
//   bid [640,704):  wq column-partials + wo row-sums.
// Last arriving block: wqs -> wa/const1/wg, then rs/d. No spins anywhere.
__global__ void __launch_bounds__(256) kA(
    const float* __restrict__ x, const float* __restrict__ cond,
    const float* __restrict__ gamma, const float* __restrict__ beta,
    const float* __restrict__ wq, const float* __restrict__ bq,
    const float* __restrict__ wk, const float* __restrict__ bk,
    const float* __restrict__ wv, const float* __restrict__ bv,
    const float* __restrict__ wo)
{
    __shared__ float smem[2 * 16 * 181];   // 23.2KB (k3 tiles); front reused elsewhere
    int t = threadIdx.x;
    int bid = blockIdx.x;
    int w = t >> 5, lane = t & 31;

    if (bid < 512) {
        // ---- x stats for (b,g) = bid ----
        const float4* xs = (const float4*)x + (size_t)bid * 16 * 256;
        float sum = 0.f, sq = 0.f;
#pragma unroll
        for (int c = 0; c < 16; c++) {
            float4 v = xs[c * 256 + t];
            sum += v.x + v.y + v.z + v.w;
            sq += v.x * v.x + v.y * v.y + v.z * v.z + v.w * v.w;
        }
        float* s1 = smem;
        float* s2 = smem + 256;
        s1[t] = sum; s2[t] = sq;
        __syncthreads();
        for (int st = 128; st; st >>= 1) {
            if (t < st) { s1[t] += s1[t + st]; s2[t] += s2[t + st]; }
            __syncthreads();
        }
        if (t == 0) { g_sum[bid] = s1[0]; g_sq[bid] = s2[0]; }
    } else if (bid < 640) {
        // ---- k/v GEMM: 16 f x 16 b per block ----
        int bx = bid - 512;               // 0..127
        int mat = bx >> 6;                // 0 = k, 1 = v
        int ft = bx & 63;                 // f-tile of 16
        const float* W    = mat ? wv : wk;
        const float* bias = mat ? bv : bk;
        float* o          = mat ? g_v : g_k;

        float (*sw)[181] = (float (*)[181])smem;
        float (*sc)[181] = (float (*)[181])(smem + 16 * 181);
        int f0 = ft * 16;
        for (int i = t; i < 16 * 180; i += 256) {
            int r = i / 180, cc2 = i - r * 180;
            sw[r][cc2] = W[(size_t)(f0 + r) * TT + cc2];
            sc[r][cc2] = cond[r * TT + cc2];
        }
        __syncthreads();

        int fo = t & 15, bb = t >> 4;
        float acc = 0.f;
#pragma unroll 4
        for (int k = 0; k < TT; k++) acc += sw[fo][k] * sc[bb][k];
        o[bb * FF + f0 + fo] = acc + bias[f0 + fo];
    } else {
        // ---- weight reductions: block j owns 8 rows of wq and wo ----
        int j = bid - 640;                // 0..63
        float s0 = 0.f, s1 = 0.f;
#pragma unroll
        for (int r = 0; r < 8; r++) {
            const float* row = wq + (size_t)(j * 8 + r) * 512;
            s0 += row[t];
            s1 += row[t + 256];
        }
        g_part[j * 512 + t] = s0;
        g_part[j * 512 + t + 256] = s1;

        // wo row sum: warp w owns row j*8+w
        const float* rp = wo + (size_t)(j * 8 + w) * 512;
        float r = 0.f;
#pragma unroll
        for (int i = 0; i < 16; i++) r += rp[lane + 32 * i];
#pragma unroll
        for (int off = 16; off; off >>= 1) r += __shfl_down_sync(0xffffffffu, r, off);
        if (lane == 0) g_Wsum[j * 8 + w] = r;
    }

    // ---- last-block election over all 704 blocks (no spin) ----
    __syncthreads();
    __threadfence();
    __shared__ int isLast;
    if (t == 0) isLast = (atomicAdd(&g_c1, 1) == 703);
    __syncthreads();
    if (!isLast) return;
    __threadfence();

    // ---- finalize weights: wqs -> wa, const1, wg ----
    float wqs0 = 0.f, wqs1 = 0.f;
#pragma unroll 8
    for (int jj = 0; jj < CARRY; jj++) {
        wqs0 += g_part[jj * 512 + t];
        wqs1 += g_part[jj * 512 + t + 256];
    }
    float wa0 = wqs0 * gamma[t];
    float wa1 = wqs1 * gamma[t + 256];
    g_wa[t] = wa0;
    g_wa[t + 256] = wa1;

    smem[t] = wqs0 * beta[t] + bq[t] + wqs1 * beta[t + 256] + bq[t + 256];
    __syncthreads();
    for (int st = 128; st; st >>= 1) {
        if (t < st) smem[t] += smem[t + st];
        __syncthreads();
    }
    float c1;
    if (t == 0) { g_const1 = smem[0]; g_c1 = 0; }  // reset ticket for replay

    // per-group (16-ch) sums of wa -> g_wg
    float wg0 = wa0, wg1 = wa1;
#pragma unroll
    for (int off = 8; off; off >>= 1) {
        wg0 += __shfl_down_sync(0xffffffffu, wg0, off, 16);
        wg1 += __shfl_down_sync(0xffffffffu, wg1, off, 16);
    }
    if ((t & 15) == 0) {
        g_wg[t >> 4] = wg0;
        g_wg[16 + (t >> 4)] = wg1;
    }
    __syncthreads();   // g_wg / g_const1 visible block-wide

    // ---- rs for all 512 (b,g); d[b] per batch ----
    float* tmp = smem + 512;   // 512 floats, clear of the const1 region
    const float inv = 1.f / 16384.f;
#pragma unroll
    for (int i = 0; i < 2; i++) {
        int idx = t + 256 * i;                 // (b*32+g)
        float mean = g_sum[idx] * inv;
        float var = g_sq[idx] * inv - mean * mean;
        float rs = rsqrtf(var + EPSF);
        g_rs[idx] = rs;
        tmp[idx] = mean * rs * g_wg[idx & 31];
    }
    __syncthreads();
    c1 = g_const1;
#pragma unroll
    for (int i = 0; i < 2; i++) {
        int b = w + 8 * i;                     // 8 warps x 2 = 16 batches
        float v = tmp[b * 32 + lane];
#pragma unroll
        for (int off = 16; off; off >>= 1) v += __shfl_down_sync(0xffffffffu, v, off);
        if (lane == 0) g_d[b] = c1 - v;
    }
}

// ---------------- kB: S from x + softmax-weighted average + output, fused ----------
// grid 512 (b = blk>>5, 32-col chunk ch = blk&31), block 256 (8 warps).
// Phase S:   S[n] = (sum_c wch[c]*x[b,c,n0+n] + d) * SCALE, coalesced warp loads.
// Phase sm:  softmax-weighted average over f -> sA[32].
// Phase out: out[b,c,n0:n0+32] = x + Wsum[c]*A[n] + bo[c]  (x re-read: L1/L2 hot).
__global__ void __launch_bounds__(256) kB(
    const float* __restrict__ x, const float* __restrict__ bo,
    float* __restrict__ out)
{
    __shared__ float sk[1024], sv[1024], wch[512], part[256], sS[32], sA[32];
    int bid = blockIdx.x;
    int b  = bid >> 5;
    int ch = bid & 31;
    int n0 = ch * 32;
    int t = threadIdx.x;
    int w = t >> 5, lane = t & 31;

    ((float4*)sk)[t] = ((const float4*)(g_k + b * FF))[t];
    ((float4*)sv)[t] = ((const float4*)(g_v + b * FF))[t];
    wch[t]       = g_rs[b * 32 + (t >> 4)] * g_wa[t];
    wch[t + 256] = g_rs[b * 32 + ((t + 256) >> 4)] * g_wa[t + 256];
    float d = g_d[b];
    __syncthreads();

    // ---- Phase S: thread t handles n = t&31, channel group cg = t>>5 (64 chans) ----
    {
        int n = t & 31, cg = t >> 5;
        const float* xb = x + ((size_t)b * 512 + cg * 64) * 1024 + n0 + n;
        float acc = 0.f;
#pragma unroll 8
        for (int k = 0; k < 64; k++) acc += wch[cg * 64 + k] * xb[(size_t)k * 1024];
        part[t] = acc;
    }
    __syncthreads();
    if (t < 32) {
        float s = 0.f;
#pragma unroll
        for (int j = 0; j < 8; j++) s += part[j * 32 + t];
        sS[t] = (s + d) * SCALE;
    }
    __syncthreads();

    // ---- Phase softmax: warp per 4 n (no max-sub: logits tiny by construction) ----
#pragma unroll
    for (int i = 0; i < 4; i++) {
        int n = w * 4 + i;
        float s = sS[n];
        float l = 0.f, acc = 0.f;
#pragma unroll
        for (int j = 0; j < 8; j++) {
            float4 k4v = ((float4*)sk)[j * 32 + lane];
            float4 v4  = ((float4*)sv)[j * 32 + lane];
            float e0 = __expf(s * k4v.x), e1 = __expf(s * k4v.y);
            float e2 = __expf(s * k4v.z), e3 = __expf(s * k4v.w);
            l += e0 + e1 + e2 + e3;
            acc += v4.x * e0 + v4.y * e1 + v4.z * e2 + v4.w * e3;
        }
#pragma unroll
        for (int off = 16; off; off >>= 1) {
            l   += __shfl_xor_sync(0xffffffffu, l, off);
            acc += __shfl_xor_sync(0xffffffffu, acc, off);
        }
        if (lane == 0) sA[n] = acc / l;
    }
    __syncthreads();

    // ---- Phase out: 32 n = 8 float4 per channel row, 512 channels ----
    int f4 = t & 7, c0 = t >> 3;
    const float4* xp = (const float4*)x + ((size_t)b * 512) * 256 + ch * 8;
    float4*       op = (float4*)out     + ((size_t)b * 512) * 256 + ch * 8;
    float4 a = ((float4*)sA)[f4];
#pragma unroll
    for (int it = 0; it < 16; it++) {
        int c = c0 + 32 * it;
        float wv_ = g_Wsum[c];
        float bb = bo[c];
        float4 xv = xp[(size_t)c * 256 + f4];
        float4 o;
        o.x = xv.x + wv_ * a.x + bb;
        o.y = xv.y + wv_ * a.y + bb;
        o.z = xv.z + wv_ * a.z + bb;
        o.w = xv.w + wv_ * a.w + bb;
        op[(size_t)c * 256 + f4] = o;
    }
}

extern "C" void kernel_launch(void* const* d_in, const int* in_sizes, int n_in,
                              void* d_out, int out_size) {
    const float* x     = (const float*)d_in[0];
    const float* cond  = (const float*)d_in[1];
    const float* gamma = (const float*)d_in[2];
    const float* beta  = (const float*)d_in[3];
    const float* wq    = (const float*)d_in[4];
    const float* bq    = (const float*)d_in[5];
    const float* wk    = (const float*)d_in[6];
    const float* bk    = (const float*)d_in[7];
    const float* wv    = (const float*)d_in[8];
    const float* bv    = (const float*)d_in[9];
    const float* wo    = (const float*)d_in[10];
    const float* bo    = (const float*)d_in[11];
    float* out = (float*)d_out;

    kA<<<704, 256>>>(x, cond, gamma, beta, wq, bq, wk, bk, wv, bv, wo);
    kB<<<512, 256>>>(x, bo, out);
}

// round 8
// speedup vs baseline: 1.3975x; 1.0481x over previous
#include <cuda_runtime.h>

// Problem constants
#define BB 16
#define GG 32
#define TT 180
#define NN 1024   // H*W
#define FF 1024
#define SCALE 0.04419417382415922f  // 512^-0.5
#define EPSF 1e-6f
#define CARRY 64  // blocks doing the wq/wo weight reduction

// ---------------- scratch (no allocs allowed) ----------------
__device__ __align__(16) float g_part[CARRY * 512];   // partial column sums of wq
__device__ __align__(16) float g_wa[512];             // wqs[c]*gamma[c]
__device__ __align__(16) float g_wg[32];              // per-group sum of wa
__device__ __align__(16) float g_Wsum[512];           // row sums of wo
__device__ float g_const1;                            // sum(wqs*beta) + sum(bq)
__device__ float g_sum[BB * GG];
__device__ float g_sq[BB * GG];
__device__ float g_rs[BB * GG];
__device__ float g_d[BB];
__device__ __align__(16) float g_k[BB * FF];
__device__ __align__(16) float g_v[BB * FF];
__device__ __align__(16) float g_A[BB * NN];
__device__ int g_c1 = 0;      // kA last-block ticket

// ---------------- kA: stats ∥ k/v GEMM ∥ weight reductions (all independent) ----------
// grid 704, block 256.
//   bid [0,512):    per-(b,g) x stats: sum, sumsq (needs NO weights).
//   bid [512,640):  k/v GEMM.
//   bid [640,704):  wq column-partials + wo row-sums.
// Last arriving block: wqs -> wa/const1/wg, then rs/d. No spins anywhere.
__global__ void __launch_bounds__(256) kA(
    const float* __restrict__ x, const float* __restrict__ cond,
    const float* __restrict__ gamma, const float* __restrict__ beta,
    const float* __restrict__ wq, const float* __restrict__ bq,
    const float* __restrict__ wk, const float* __restrict__ bk,
    const float* __restrict__ wv, const float* __restrict__ bv,
    const float* __restrict__ wo)
{
    __shared__ float smem[2 * 16 * 181];   // 23.2KB (k3 tiles); front reused elsewhere
    int t = threadIdx.x;
    int bid = blockIdx.x;
    int w = t >> 5, lane = t & 31;

    if (bid < 512) {
        // ---- x stats for (b,g) = bid ----
        const float4* xs = (const float4*)x + (size_t)bid * 16 * 256;
        float sum = 0.f, sq = 0.f;
#pragma unroll
        for (int c = 0; c < 16; c++) {
            float4 v = xs[c * 256 + t];
            sum += v.x + v.y + v.z + v.w;
            sq += v.x * v.x + v.y * v.y + v.z * v.z + v.w * v.w;
        }
        float* s1 = smem;
        float* s2 = smem + 256;
        s1[t] = sum; s2[t] = sq;
        __syncthreads();
        for (int st = 128; st; st >>= 1) {
            if (t < st) { s1[t] += s1[t + st]; s2[t] += s2[t + st]; }
            __syncthreads();
        }
        if (t == 0) { g_sum[bid] = s1[0]; g_sq[bid] = s2[0]; }
    } else if (bid < 640) {
        // ---- k/v GEMM: 16 f x 16 b per block ----
        int bx = bid - 512;               // 0..127
        int mat = bx >> 6;                // 0 = k, 1 = v
        int ft = bx & 63;                 // f-tile of 16
        const float* W    = mat ? wv : wk;
        const float* bias = mat ? bv : bk;
        float* o          = mat ? g_v : g_k;

        float (*sw)[181] = (float (*)[181])smem;
        float (*sc)[181] = (float (*)[181])(smem + 16 * 181);
        int f0 = ft * 16;
        for (int i = t; i < 16 * 180; i += 256) {
            int r = i / 180, cc2 = i - r * 180;
            sw[r][cc2] = W[(size_t)(f0 + r) * TT + cc2];
            sc[r][cc2] = cond[r * TT + cc2];
        }
        __syncthreads();

        int fo = t & 15, bb = t >> 4;
        float acc = 0.f;
#pragma unroll 4
        for (int k = 0; k < TT; k++) acc += sw[fo][k] * sc[bb][k];
        o[bb * FF + f0 + fo] = acc + bias[f0 + fo];
    } else {
        // ---- weight reductions: block j owns 8 rows of wq and wo ----
        int j = bid - 640;                // 0..63
        float s0 = 0.f, s1 = 0.f;
#pragma unroll
        for (int r = 0; r < 8; r++) {
            const float* row = wq + (size_t)(j * 8 + r) * 512;
            s0 += row[t];
            s1 += row[t + 256];
        }
        g_part[j * 512 + t] = s0;
        g_part[j * 512 + t + 256] = s1;

        // wo row sum: warp w owns row j*8+w
        const float* rp = wo + (size_t)(j * 8 + w) * 512;
        float r = 0.f;
#pragma unroll
        for (int i = 0; i < 16; i++) r += rp[lane + 32 * i];
#pragma unroll
        for (int off = 16; off; off >>= 1) r += __shfl_down_sync(0xffffffffu, r, off);
        if (lane == 0) g_Wsum[j * 8 + w] = r;
    }

    // ---- last-block election over all 704 blocks (no spin) ----
    __syncthreads();
    __threadfence();
    __shared__ int isLast;
    if (t == 0) isLast = (atomicAdd(&g_c1, 1) == 703);
    __syncthreads();
    if (!isLast) return;
    __threadfence();

    // ---- finalize weights: wqs -> wa, const1, wg ----
    float wqs0 = 0.f, wqs1 = 0.f;
#pragma unroll 8
    for (int jj = 0; jj < CARRY; jj++) {
        wqs0 += g_part[jj * 512 + t];
        wqs1 += g_part[jj * 512 + t + 256];
    }
    float wa0 = wqs0 * gamma[t];
    float wa1 = wqs1 * gamma[t + 256];
    g_wa[t] = wa0;
    g_wa[t + 256] = wa1;

    smem[t] = wqs0 * beta[t] + bq[t] + wqs1 * beta[t + 256] + bq[t + 256];
    __syncthreads();
    for (int st = 128; st; st >>= 1) {
        if (t < st) smem[t] += smem[t + st];
        __syncthreads();
    }
    float c1;
    if (t == 0) { g_const1 = smem[0]; g_c1 = 0; }  // reset ticket for replay

    // per-group (16-ch) sums of wa -> g_wg
    float wg0 = wa0, wg1 = wa1;
#pragma unroll
    for (int off = 8; off; off >>= 1) {
        wg0 += __shfl_down_sync(0xffffffffu, wg0, off, 16);
        wg1 += __shfl_down_sync(0xffffffffu, wg1, off, 16);
    }
    if ((t & 15) == 0) {
        g_wg[t >> 4] = wg0;
        g_wg[16 + (t >> 4)] = wg1;
    }
    __syncthreads();   // g_wg / g_const1 visible block-wide

    // ---- rs for all 512 (b,g); d[b] per batch ----
    float* tmp = smem + 512;   // 512 floats, clear of the const1 region
    const float inv = 1.f / 16384.f;
#pragma unroll
    for (int i = 0; i < 2; i++) {
        int idx = t + 256 * i;                 // (b*32+g)
        float mean = g_sum[idx] * inv;
        float var = g_sq[idx] * inv - mean * mean;
        float rs = rsqrtf(var + EPSF);
        g_rs[idx] = rs;
        tmp[idx] = mean * rs * g_wg[idx & 31];
    }
    __syncthreads();
    c1 = g_const1;
#pragma unroll
    for (int i = 0; i < 2; i++) {
        int b = w + 8 * i;                     // 8 warps x 2 = 16 batches
        float v = tmp[b * 32 + lane];
#pragma unroll
        for (int off = 16; off; off >>= 1) v += __shfl_down_sync(0xffffffffu, v, off);
        if (lane == 0) g_d[b] = c1 - v;
    }
}

// ---------------- kC: S from x + softmax-weighted average -> g_A ----------------
// grid 256 (b = blk>>4, 64-n chunk = blk&15), block 256 (8 warps).
__global__ void __launch_bounds__(256) kC(const float* __restrict__ x)
{
    __shared__ float sk[1024], sv[1024], wch[512], part[256], sS[64];
    int bid = blockIdx.x;
    int b  = bid >> 4;
    int nc = bid & 15;
    int n0 = nc * 64;
    int t = threadIdx.x;
    int w = t >> 5, lane = t & 31;

    ((float4*)sk)[t] = ((const float4*)(g_k + b * FF))[t];
    ((float4*)sv)[t] = ((const float4*)(g_v + b * FF))[t];
    wch[t]       = g_rs[b * 32 + (t >> 4)] * g_wa[t];
    wch[t + 256] = g_rs[b * 32 + ((t + 256) >> 4)] * g_wa[t + 256];
    float d = g_d[b];
    __syncthreads();

    // ---- Phase S: thread t handles n = t&63, channel group cg = t>>6 (128 chans) ----
    {
        int n = t & 63, cg = t >> 6;
        const float* xb = x + ((size_t)b * 512 + cg * 128) * 1024 + n0 + n;
        float acc = 0.f;
#pragma unroll 16
        for (int k = 0; k < 128; k++) acc += wch[cg * 128 + k] * xb[(size_t)k * 1024];
        part[t] = acc;
    }
    __syncthreads();
    if (t < 64)
        sS[t] = (part[t] + part[t + 64] + part[t + 128] + part[t + 192] + d) * SCALE;
    __syncthreads();

    // ---- softmax-weighted average (no max-sub: logits tiny by construction) ----
#pragma unroll
    for (int i = 0; i < 8; i++) {
        int n = w * 8 + i;
        float s = sS[n];
        float l = 0.f, acc = 0.f;
#pragma unroll
        for (int j = 0; j < 8; j++) {
            float4 k4v = ((float4*)sk)[j * 32 + lane];
            float4 v4  = ((float4*)sv)[j * 32 + lane];
            float e0 = __expf(s * k4v.x), e1 = __expf(s * k4v.y);
            float e2 = __expf(s * k4v.z), e3 = __expf(s * k4v.w);
            l += e0 + e1 + e2 + e3;
            acc += v4.x * e0 + v4.y * e1 + v4.z * e2 + v4.w * e3;
        }
#pragma unroll
        for (int off = 16; off; off >>= 1) {
            l   += __shfl_xor_sync(0xffffffffu, l, off);
            acc += __shfl_xor_sync(0xffffffffu, acc, off);
        }
        if (lane == 0) g_A[b * NN + n0 + n] = acc / l;
    }
}

// ---------------- kD: out = x + Wsum[c]*A[b,n] + bo[c], pure linear stream -------
// float4 over n. 8192 blocks x 256.
__global__ void __launch_bounds__(256) kD(
    const float* __restrict__ x, const float* __restrict__ bo,
    float* __restrict__ out)
{
    size_t i = (size_t)blockIdx.x * 256 + threadIdx.x;  // float4 index
    int n4 = (int)(i & 255);
    int c = (int)((i >> 8) & 511);
    int b = (int)(i >> 17);
    float4 xv = ((const float4*)x)[i];
    float4 av = ((const float4*)g_A)[b * 256 + n4];
    float wv = g_Wsum[c];
    float bb = bo[c];
    float4 o;
    o.x = xv.x + wv * av.x + bb;
    o.y = xv.y + wv * av.y + bb;
    o.z = xv.z + wv * av.z + bb;
    o.w = xv.w + wv * av.w + bb;
    ((float4*)out)[i] = o;
}

extern "C" void kernel_launch(void* const* d_in, const int* in_sizes, int n_in,
                              void* d_out, int out_size) {
    const float* x     = (const float*)d_in[0];
    const float* cond  = (const float*)d_in[1];
    const float* gamma = (const float*)d_in[2];
    const float* beta  = (const float*)d_in[3];
    const float* wq    = (const float*)d_in[4];
    const float* bq    = (const float*)d_in[5];
    const float* wk    = (const float*)d_in[6];
    const float* bk    = (const float*)d_in[7];
    const float* wv    = (const float*)d_in[8];
    const float* bv    = (const float*)d_in[9];
    const float* wo    = (const float*)d_in[10];
    const float* bo    = (const float*)d_in[11];
    float* out = (float*)d_out;

    kA<<<704, 256>>>(x, cond, gamma, beta, wq, bq, wk, bk, wv, bv, wo);
    kC<<<256, 256>>>(x);
    kD<<<8192, 256>>>(x, bo, out);
}